// round 1
// baseline (speedup 1.0000x reference)
#include <cuda_runtime.h>
#include <math.h>

#define Natoms 1024
#define Hdim   256
#define Ldim   512
#define NGs    50
#define NIs    3
#define Bmol   16
#define NGRID  8192
#define CUT    5.0f
#define TR     16

// scratch (no allocations allowed)
__device__ float g_h[Natoms*Hdim];
__device__ float g_agg[Natoms*Hdim];
__device__ float g_tmp[Natoms*Hdim];
__device__ float g_tab[NGRID*Hdim];     // 8 MB filter table (per current layer)
__device__ float g_pool[Bmol*Hdim];

__device__ __forceinline__ float gelu_f(float x){
    return 0.5f*x*(1.0f+erff(x*0.70710678118654752f));
}

// ---------------------------------------------------------------- embedding
__global__ void k_embed(const int* __restrict__ z, const float* __restrict__ emb){
    int i=blockIdx.x, c=threadIdx.x;
    g_h[i*Hdim+c]=emb[z[i]*Hdim+c];
}

// ------------------------------------------------- filter table build (1 layer)
// Wtab[r,:] = gelu(rbf(d_r)@fw1 + fb1) @ fw2 + fb2,  d_r = r * CUT/(NGRID-1)
__global__ void k_table(const float* __restrict__ fw1, const float* __restrict__ fb1,
                        const float* __restrict__ fw2, const float* __restrict__ fb2){
    __shared__ float rbf[TR][NGs];
    __shared__ float Gs[Hdim][TR+2];           // transposed, padded
    int r0=blockIdx.x*TR;
    int c=threadIdx.x;
    const float dstep  = CUT/(float)(NGRID-1);
    const float cstep  = CUT/(float)(NGs-1);   // linspace(0,5,50)
    const float inv2w2 = 1.0f/(2.0f*0.05f*0.05f);   // WIDTH = 0.5*(CUT/NG) = 0.05

    for(int t=c;t<TR*NGs;t+=blockDim.x){
        int row=t/NGs, g=t%NGs;
        float d=(float)(r0+row)*dstep;
        float u=d-(float)g*cstep;
        rbf[row][g]=expf(-u*u*inv2w2);
    }
    __syncthreads();

    float acc[TR];
    float b1=fb1[c];
    #pragma unroll
    for(int t=0;t<TR;t++) acc[t]=b1;
    for(int g=0;g<NGs;g++){
        float w=fw1[g*Hdim+c];
        #pragma unroll
        for(int t=0;t<TR;t++) acc[t]=fmaf(rbf[t][g],w,acc[t]);
    }
    #pragma unroll
    for(int t=0;t<TR;t++) Gs[c][t]=gelu_f(acc[t]);
    __syncthreads();

    float b2=fb2[c];
    float accw[TR];
    #pragma unroll
    for(int t=0;t<TR;t++) accw[t]=b2;
    for(int k=0;k<Hdim;k++){
        float w2=fw2[k*Hdim+c];
        #pragma unroll
        for(int t=0;t<TR;t++) accw[t]=fmaf(Gs[k][t],w2,accw[t]);
    }
    #pragma unroll
    for(int t=0;t<TR;t++) g_tab[(r0+t)*Hdim+c]=accw[t];
}

// ----------------------------------------- neighbor aggregation (1 CTA / atom)
__global__ void k_agg(const float* __restrict__ pos){
    __shared__ int   jl[Natoms];
    __shared__ float dl[Natoms];
    __shared__ int   warp_cnt[8];
    int i=blockIdx.x, tid=threadIdx.x;
    float xi=pos[i*3+0], yi=pos[i*3+1], zi=pos[i*3+2];

    // deterministic (j-ordered) stream compaction of neighbors
    int total=0;
    for(int base=0;base<Natoms;base+=256){
        int j=base+tid;
        float dx=pos[j*3+0]-xi;
        float dy=pos[j*3+1]-yi;
        float dz=pos[j*3+2]-zi;
        float d=sqrtf(dx*dx+dy*dy+dz*dz);
        bool keep=(j!=i)&&(d<CUT)&&(d>1e-6f);
        unsigned m=__ballot_sync(0xffffffffu,keep);
        if((tid&31)==0) warp_cnt[tid>>5]=__popc(m);
        __syncthreads();
        int off=total;
        int w=tid>>5;
        for(int ww=0;ww<w;ww++) off+=warp_cnt[ww];
        if(keep){
            int p=off+__popc(m&((1u<<(tid&31))-1u));
            jl[p]=j; dl[p]=d;
        }
        int bt=0;
        #pragma unroll
        for(int ww=0;ww<8;ww++) bt+=warp_cnt[ww];
        total+=bt;
        __syncthreads();
    }

    // lerp the tabulated filter, multiply by h[j], accumulate
    const float scale=(float)(NGRID-1)/CUT;
    float acc=0.0f;
    int c=tid;
    #pragma unroll 4
    for(int n=0;n<total;n++){
        int j=jl[n];
        float t=dl[n]*scale;
        int r=(int)t;
        r = (r>NGRID-2) ? (NGRID-2) : r;
        float f=t-(float)r;
        float w0=g_tab[r*Hdim+c];
        float w1=g_tab[(r+1)*Hdim+c];
        float w=fmaf(f,w1-w0,w0);
        acc=fmaf(w,g_h[j*Hdim+c],acc);
    }
    g_agg[i*Hdim+c]=acc;
}

// ------------------------------------------------ tiled GEMM  C = act(A@W + b) [+Res]
// A:[M,256] W:[256,256]. grid (M/64, 4), 256 threads, 4x4 micro-tile.
template<bool GELU,bool RES>
__global__ void k_gemm(const float* __restrict__ A, const float* __restrict__ W,
                       const float* __restrict__ bias, const float* Res, float* C){
    __shared__ float As[16][68];
    __shared__ float Bs[16][68];
    int m0=blockIdx.x*64, n0=blockIdx.y*64;
    int tid=threadIdx.x;
    int tm=tid>>4, tn=tid&15;
    float acc[4][4];
    #pragma unroll
    for(int u=0;u<4;u++)
        #pragma unroll
        for(int v=0;v<4;v++) acc[u][v]=0.f;
    int ar=tid>>2, ak=(tid&3)<<2;
    int bk=tid>>4, bn=(tid&15)<<2;
    for(int k0=0;k0<Hdim;k0+=16){
        float4 av=*reinterpret_cast<const float4*>(&A[(m0+ar)*Hdim+k0+ak]);
        As[ak+0][ar]=av.x; As[ak+1][ar]=av.y; As[ak+2][ar]=av.z; As[ak+3][ar]=av.w;
        float4 bv=*reinterpret_cast<const float4*>(&W[(k0+bk)*Hdim+n0+bn]);
        *reinterpret_cast<float4*>(&Bs[bk][bn])=bv;
        __syncthreads();
        #pragma unroll
        for(int k=0;k<16;k++){
            float a[4],b[4];
            #pragma unroll
            for(int u=0;u<4;u++){a[u]=As[k][tm*4+u]; b[u]=Bs[k][tn*4+u];}
            #pragma unroll
            for(int u=0;u<4;u++)
                #pragma unroll
                for(int v=0;v<4;v++) acc[u][v]=fmaf(a[u],b[v],acc[u][v]);
        }
        __syncthreads();
    }
    #pragma unroll
    for(int u=0;u<4;u++){
        int row=m0+tm*4+u;
        #pragma unroll
        for(int v=0;v<4;v++){
            int col=n0+tn*4+v;
            float x=acc[u][v]+bias[col];
            if(GELU) x=gelu_f(x);
            if(RES)  x+=Res[row*Hdim+col];
            C[row*Hdim+col]=x;
        }
    }
}

// ---------------------------------------------------------------- pooling
__global__ void k_pool(const int* __restrict__ batch){
    int b=blockIdx.x, c=threadIdx.x;
    float s=0.f;
    for(int i=0;i<Natoms;i++){
        if(batch[i]==b) s+=g_h[i*Hdim+c];
    }
    g_pool[b*Hdim+c]=s;
}

// ------------------------------------------------- projection head + layernorm
__global__ void k_head(const float* __restrict__ pw1,const float* __restrict__ pb1,
                       const float* __restrict__ pw2,const float* __restrict__ pb2,
                       const float* __restrict__ lng,const float* __restrict__ lnb,
                       float* __restrict__ out){
    __shared__ float pv[Hdim];
    __shared__ float tv[Hdim];
    __shared__ float xv[Ldim];
    __shared__ float red[8];
    __shared__ float s_mu, s_inv;
    int b=blockIdx.x, tid=threadIdx.x;
    pv[tid]=g_pool[b*Hdim+tid];
    __syncthreads();
    float a=pb1[tid];
    for(int k=0;k<Hdim;k++) a=fmaf(pv[k],pw1[k*Hdim+tid],a);
    tv[tid]=gelu_f(a);
    __syncthreads();
    for(int o=tid;o<Ldim;o+=256){
        float x=pb2[o];
        for(int k=0;k<Hdim;k++) x=fmaf(tv[k],pw2[k*Ldim+o],x);
        xv[o]=x;
    }
    __syncthreads();
    // mean
    float s=xv[tid]+xv[tid+256];
    for(int d=16;d>0;d>>=1) s+=__shfl_down_sync(0xffffffffu,s,d);
    if((tid&31)==0) red[tid>>5]=s;
    __syncthreads();
    if(tid==0){
        float t=0.f; for(int w=0;w<8;w++) t+=red[w];
        s_mu=t/(float)Ldim;
    }
    __syncthreads();
    float mu=s_mu;
    float d0=xv[tid]-mu, d1=xv[tid+256]-mu;
    float s2=d0*d0+d1*d1;
    for(int d=16;d>0;d>>=1) s2+=__shfl_down_sync(0xffffffffu,s2,d);
    if((tid&31)==0) red[tid>>5]=s2;
    __syncthreads();
    if(tid==0){
        float t=0.f; for(int w=0;w<8;w++) t+=red[w];
        s_inv=1.0f/sqrtf(t/(float)Ldim + 1e-5f);
    }
    __syncthreads();
    float inv=s_inv;
    out[b*Ldim+tid]     =(xv[tid]-mu)*inv*lng[tid]+lnb[tid];
    out[b*Ldim+tid+256] =(xv[tid+256]-mu)*inv*lng[tid+256]+lnb[tid+256];
}

// ------------------------------------------------------------------ launcher
extern "C" void kernel_launch(void* const* d_in, const int* in_sizes, int n_in,
                              void* d_out, int out_size){
    const int*   z    =(const int*)  d_in[0];
    const float* pos  =(const float*)d_in[1];
    const int*   batch=(const int*)  d_in[2];
    const float* emb  =(const float*)d_in[3];
    const float* fw1  =(const float*)d_in[4];
    const float* fb1  =(const float*)d_in[5];
    const float* fw2  =(const float*)d_in[6];
    const float* fb2  =(const float*)d_in[7];
    const float* aw1  =(const float*)d_in[8];
    const float* ab1  =(const float*)d_in[9];
    const float* aw2  =(const float*)d_in[10];
    const float* ab2  =(const float*)d_in[11];
    const float* pw1  =(const float*)d_in[12];
    const float* pb1  =(const float*)d_in[13];
    const float* pw2  =(const float*)d_in[14];
    const float* pb2  =(const float*)d_in[15];
    const float* lng  =(const float*)d_in[16];
    const float* lnb  =(const float*)d_in[17];
    float* out=(float*)d_out;

    float *pagg,*ptmp,*ph;
    cudaGetSymbolAddress((void**)&pagg,g_agg);
    cudaGetSymbolAddress((void**)&ptmp,g_tmp);
    cudaGetSymbolAddress((void**)&ph,  g_h);

    k_embed<<<Natoms,Hdim>>>(z,emb);
    for(int l=0;l<NIs;l++){
        k_table<<<NGRID/TR,Hdim>>>(fw1+l*NGs*Hdim, fb1+l*Hdim,
                                   fw2+l*Hdim*Hdim, fb2+l*Hdim);
        k_agg<<<Natoms,Hdim>>>(pos);
        k_gemm<true ,false><<<dim3(Natoms/64,Hdim/64),256>>>(pagg, aw1+l*Hdim*Hdim, ab1+l*Hdim, nullptr, ptmp);
        k_gemm<false,true ><<<dim3(Natoms/64,Hdim/64),256>>>(ptmp, aw2+l*Hdim*Hdim, ab2+l*Hdim, ph, ph);
    }
    k_pool<<<Bmol,Hdim>>>(batch);
    k_head<<<Bmol,Hdim>>>(pw1,pb1,pw2,pb2,lng,lnb,out);
}

// round 2
// speedup vs baseline: 1.2175x; 1.2175x over previous
#include <cuda_runtime.h>
#include <cuda_fp16.h>
#include <math.h>

#define Natoms 1024
#define Hdim   256
#define Ldim   512
#define NGs    50
#define NIs    3
#define Bmol   16
#define NGRID  2048
#define CUT    5.0f
#define TR     16

typedef unsigned long long ull;

// scratch (no allocations allowed)
__device__ float  g_h[Natoms*Hdim];
__device__ __half g_hh[Natoms*Hdim];        // fp16 mirror of h
__device__ float  g_agg[Natoms*Hdim];
__device__ float  g_tmp[Natoms*Hdim];
__device__ float  g_G[NGRID*Hdim];          // gelu hidden of table MLP
__device__ __half g_tab[NGRID*Hdim];        // fp16 filter table (1 MB)
__device__ float  g_pool[Bmol*Hdim];
__device__ unsigned g_nbr[Natoms*Natoms];   // packed neighbor list
__device__ int      g_cnt[Natoms];

__device__ __forceinline__ float gelu_f(float x){
    return 0.5f*x*(1.0f+erff(x*0.70710678118654752f));
}
__device__ __forceinline__ void ffma2(ull& d, ull a, ull b){
    asm("fma.rn.f32x2 %0, %1, %2, %0;" : "+l"(d) : "l"(a), "l"(b));
}
__device__ __forceinline__ float2 unpk(ull v){
    float2 r; asm("mov.b64 {%0,%1}, %2;" : "=f"(r.x), "=f"(r.y) : "l"(v)); return r;
}

// ---------------------------------------------------------------- embedding
__global__ void k_embed(const int* __restrict__ z, const float* __restrict__ emb){
    int i=blockIdx.x, c=threadIdx.x;
    float v=emb[z[i]*Hdim+c];
    g_h[i*Hdim+c]=v;
    g_hh[i*Hdim+c]=__float2half(v);
}

// ------------------------------------------------ neighbor list (built once)
// packed: j(10) | r(11)<<10 | fq(11)<<21
__global__ void k_nbr(const float* __restrict__ pos){
    __shared__ int warp_cnt[8];
    int i=blockIdx.x, tid=threadIdx.x;
    float xi=pos[i*3+0], yi=pos[i*3+1], zi=pos[i*3+2];
    const float scale=(float)(NGRID-1)/CUT;
    int total=0;
    for(int base=0;base<Natoms;base+=256){
        int j=base+tid;
        float dx=pos[j*3+0]-xi;
        float dy=pos[j*3+1]-yi;
        float dz=pos[j*3+2]-zi;
        float d=sqrtf(dx*dx+dy*dy+dz*dz);
        bool keep=(j!=i)&&(d<CUT)&&(d>1e-6f);
        unsigned m=__ballot_sync(0xffffffffu,keep);
        if((tid&31)==0) warp_cnt[tid>>5]=__popc(m);
        __syncthreads();
        int off=total;
        int w=tid>>5;
        for(int ww=0;ww<w;ww++) off+=warp_cnt[ww];
        if(keep){
            int p=off+__popc(m&((1u<<(tid&31))-1u));
            float t=d*scale;
            int r=(int)t; if(r>NGRID-2)r=NGRID-2;
            float f=t-(float)r;
            int fq=(int)(f*2048.0f); if(fq>2047)fq=2047;
            g_nbr[i*Natoms+p]=(unsigned)j | ((unsigned)r<<10) | ((unsigned)fq<<21);
        }
        int bt=0;
        #pragma unroll
        for(int ww=0;ww<8;ww++) bt+=warp_cnt[ww];
        total+=bt;
        __syncthreads();
    }
    if(tid==0) g_cnt[i]=total;
}

// --------------------------------- table hidden: G = gelu(rbf @ fw1 + fb1)
__global__ void k_hidden(const float* __restrict__ fw1, const float* __restrict__ fb1){
    __shared__ float rbf[TR][52];
    int r0=blockIdx.x*TR, c=threadIdx.x;
    const float dstep  = CUT/(float)(NGRID-1);
    const float cstep  = CUT/(float)(NGs-1);
    const float inv2w2 = 1.0f/(2.0f*0.05f*0.05f);
    for(int t=c;t<TR*NGs;t+=256){
        int row=t/NGs, g=t%NGs;
        float d=(float)(r0+row)*dstep;
        float u=d-(float)g*cstep;
        rbf[row][g]=expf(-u*u*inv2w2);
    }
    __syncthreads();
    float acc[TR];
    float b1=fb1[c];
    #pragma unroll
    for(int t=0;t<TR;t++) acc[t]=b1;
    for(int g=0;g<NGs;g++){
        float w=fw1[g*Hdim+c];
        #pragma unroll
        for(int t=0;t<TR;t++) acc[t]=fmaf(rbf[t][g],w,acc[t]);
    }
    #pragma unroll
    for(int t=0;t<TR;t++) g_G[(r0+t)*Hdim+c]=gelu_f(acc[t]);
}

// --------------------------- GEMM  C = act(A@W + b) [+Res], 32x64 tiles
// A:[M,256] W:[256,256]. grid (M/32, 4), 256 threads, 2x4 micro-tile,
// k-parity packed accumulators via fma.rn.f32x2.
template<bool GELU,bool RES,bool HALF_OUT,bool WRITEH>
__global__ void __launch_bounds__(256) k_gemm(const float* __restrict__ A,
                       const float* __restrict__ W,
                       const float* __restrict__ bias,
                       const float* __restrict__ Res,
                       float* __restrict__ Cf, __half* __restrict__ Ch){
    __shared__ __align__(16) float As[32][20];
    __shared__ __align__(16) float Bs[64][22];
    int m0=blockIdx.x*32, n0=blockIdx.y*64;
    int tid=threadIdx.x;
    int tm=tid>>4;          // 0..15 -> rows tm*2, tm*2+1
    int tn=tid&15;          // cols tn*4..+3
    ull acc[2][4];
    #pragma unroll
    for(int u=0;u<2;u++)
        #pragma unroll
        for(int v=0;v<4;v++) acc[u][v]=0ull;

    for(int k0=0;k0<Hdim;k0+=16){
        if(tid<128){
            int ar=tid>>2, ak=(tid&3)<<2;
            float4 av=*reinterpret_cast<const float4*>(&A[(m0+ar)*Hdim+k0+ak]);
            *reinterpret_cast<float4*>(&As[ar][ak])=av;
        }
        {
            int bk=tid>>4, bn=(tid&15)<<2;
            float4 bv=*reinterpret_cast<const float4*>(&W[(k0+bk)*Hdim+n0+bn]);
            Bs[bn+0][bk]=bv.x; Bs[bn+1][bk]=bv.y; Bs[bn+2][bk]=bv.z; Bs[bn+3][bk]=bv.w;
        }
        __syncthreads();
        #pragma unroll
        for(int kp=0;kp<8;kp++){
            ull a0=*reinterpret_cast<const ull*>(&As[tm*2+0][kp*2]);
            ull a1=*reinterpret_cast<const ull*>(&As[tm*2+1][kp*2]);
            #pragma unroll
            for(int v=0;v<4;v++){
                ull bb=*reinterpret_cast<const ull*>(&Bs[tn*4+v][kp*2]);
                ffma2(acc[0][v],a0,bb);
                ffma2(acc[1][v],a1,bb);
            }
        }
        __syncthreads();
    }
    #pragma unroll
    for(int u=0;u<2;u++){
        int row=m0+tm*2+u;
        #pragma unroll
        for(int v=0;v<4;v++){
            int col=n0+tn*4+v;
            float2 s=unpk(acc[u][v]);
            float x=s.x+s.y+bias[col];
            if(GELU) x=gelu_f(x);
            if(RES)  x+=Res[row*Hdim+col];
            if(HALF_OUT) Ch[row*Hdim+col]=__float2half(x);
            else         Cf[row*Hdim+col]=x;
            if(WRITEH)   g_hh[row*Hdim+col]=__float2half(x);
        }
    }
}

// ----------------------------------------- neighbor aggregation (fp16 lerp)
__global__ void __launch_bounds__(128) k_agg(){
    __shared__ unsigned lst[Natoms];
    int i=blockIdx.x, tid=threadIdx.x;
    int total=g_cnt[i];
    for(int t=tid;t<total;t+=128) lst[t]=g_nbr[i*Natoms+t];
    __syncthreads();
    const __half2* __restrict__ tab=reinterpret_cast<const __half2*>(g_tab);
    const __half2* __restrict__ hh =reinterpret_cast<const __half2*>(g_hh);
    int c=tid;                 // half2 channel index 0..127
    float ax=0.f, ay=0.f;
    #pragma unroll 4
    for(int n=0;n<total;n++){
        unsigned p=lst[n];
        int j=p&1023;
        int r=(p>>10)&2047;
        float f=(float)(p>>21)*(1.0f/2048.0f);
        __half2 w0=tab[r*128+c];
        __half2 w1=tab[(r+1)*128+c];
        __half2 hv=hh[j*128+c];
        float2 a0=__half22float2(w0);
        float2 a1=__half22float2(w1);
        float2 hf=__half22float2(hv);
        float wx=fmaf(f,a1.x-a0.x,a0.x);
        float wy=fmaf(f,a1.y-a0.y,a0.y);
        ax=fmaf(wx,hf.x,ax);
        ay=fmaf(wy,hf.y,ay);
    }
    g_agg[i*Hdim+2*c+0]=ax;
    g_agg[i*Hdim+2*c+1]=ay;
}

// ---------------------------------------------------------------- pooling
__global__ void k_pool(const int* __restrict__ batch){
    int b=blockIdx.x, c=threadIdx.x;
    float s=0.f;
    #pragma unroll 8
    for(int i=0;i<Natoms;i++){
        s += (batch[i]==b) ? g_h[i*Hdim+c] : 0.f;
    }
    g_pool[b*Hdim+c]=s;
}

// ------------------------------------------------- projection head + layernorm
__global__ void k_head(const float* __restrict__ pw1,const float* __restrict__ pb1,
                       const float* __restrict__ pw2,const float* __restrict__ pb2,
                       const float* __restrict__ lng,const float* __restrict__ lnb,
                       float* __restrict__ out){
    __shared__ float pv[Hdim];
    __shared__ float tv[Hdim];
    __shared__ float xv[Ldim];
    __shared__ float red[8];
    __shared__ float s_mu, s_inv;
    int b=blockIdx.x, tid=threadIdx.x;
    pv[tid]=g_pool[b*Hdim+tid];
    __syncthreads();
    float a=pb1[tid];
    for(int k=0;k<Hdim;k++) a=fmaf(pv[k],pw1[k*Hdim+tid],a);
    tv[tid]=gelu_f(a);
    __syncthreads();
    for(int o=tid;o<Ldim;o+=256){
        float x=pb2[o];
        for(int k=0;k<Hdim;k++) x=fmaf(tv[k],pw2[k*Ldim+o],x);
        xv[o]=x;
    }
    __syncthreads();
    float s=xv[tid]+xv[tid+256];
    for(int d=16;d>0;d>>=1) s+=__shfl_down_sync(0xffffffffu,s,d);
    if((tid&31)==0) red[tid>>5]=s;
    __syncthreads();
    if(tid==0){
        float t=0.f; for(int w=0;w<8;w++) t+=red[w];
        s_mu=t/(float)Ldim;
    }
    __syncthreads();
    float mu=s_mu;
    float d0=xv[tid]-mu, d1=xv[tid+256]-mu;
    float s2=d0*d0+d1*d1;
    for(int d=16;d>0;d>>=1) s2+=__shfl_down_sync(0xffffffffu,s2,d);
    if((tid&31)==0) red[tid>>5]=s2;
    __syncthreads();
    if(tid==0){
        float t=0.f; for(int w=0;w<8;w++) t+=red[w];
        s_inv=1.0f/sqrtf(t/(float)Ldim + 1e-5f);
    }
    __syncthreads();
    float inv=s_inv;
    out[b*Ldim+tid]     =(xv[tid]-mu)*inv*lng[tid]+lnb[tid];
    out[b*Ldim+tid+256] =(xv[tid+256]-mu)*inv*lng[tid+256]+lnb[tid+256];
}

// ------------------------------------------------------------------ launcher
extern "C" void kernel_launch(void* const* d_in, const int* in_sizes, int n_in,
                              void* d_out, int out_size){
    const int*   z    =(const int*)  d_in[0];
    const float* pos  =(const float*)d_in[1];
    const int*   batch=(const int*)  d_in[2];
    const float* emb  =(const float*)d_in[3];
    const float* fw1  =(const float*)d_in[4];
    const float* fb1  =(const float*)d_in[5];
    const float* fw2  =(const float*)d_in[6];
    const float* fb2  =(const float*)d_in[7];
    const float* aw1  =(const float*)d_in[8];
    const float* ab1  =(const float*)d_in[9];
    const float* aw2  =(const float*)d_in[10];
    const float* ab2  =(const float*)d_in[11];
    const float* pw1  =(const float*)d_in[12];
    const float* pb1  =(const float*)d_in[13];
    const float* pw2  =(const float*)d_in[14];
    const float* pb2  =(const float*)d_in[15];
    const float* lng  =(const float*)d_in[16];
    const float* lnb  =(const float*)d_in[17];
    float* out=(float*)d_out;

    float *pagg,*ptmp,*ph,*pG;
    __half *ptab;
    cudaGetSymbolAddress((void**)&pagg,g_agg);
    cudaGetSymbolAddress((void**)&ptmp,g_tmp);
    cudaGetSymbolAddress((void**)&ph,  g_h);
    cudaGetSymbolAddress((void**)&pG,  g_G);
    cudaGetSymbolAddress((void**)&ptab,g_tab);

    k_embed<<<Natoms,Hdim>>>(z,emb);
    k_nbr<<<Natoms,256>>>(pos);
    for(int l=0;l<NIs;l++){
        k_hidden<<<NGRID/TR,Hdim>>>(fw1+l*NGs*Hdim, fb1+l*Hdim);
        // table = G @ fw2 + fb2  (fp16 out)
        k_gemm<false,false,true ,false><<<dim3(NGRID/32,Hdim/64),256>>>(pG, fw2+l*Hdim*Hdim, fb2+l*Hdim, nullptr, nullptr, ptab);
        k_agg<<<Natoms,128>>>();
        k_gemm<true ,false,false,false><<<dim3(Natoms/32,Hdim/64),256>>>(pagg, aw1+l*Hdim*Hdim, ab1+l*Hdim, nullptr, ptmp, nullptr);
        k_gemm<false,true ,false,true ><<<dim3(Natoms/32,Hdim/64),256>>>(ptmp, aw2+l*Hdim*Hdim, ab2+l*Hdim, ph, ph, nullptr);
    }
    k_pool<<<Bmol,Hdim>>>(batch);
    k_head<<<Bmol,Hdim>>>(pw1,pb1,pw2,pb2,lng,lnb,out);
}

// round 3
// speedup vs baseline: 1.6166x; 1.3278x over previous
#include <cuda_runtime.h>
#include <cuda_fp16.h>
#include <math.h>

#define Natoms 1024
#define Hdim   256
#define Ldim   512
#define NGs    50
#define NIs    3
#define Bmol   16
#define NGRID  2048
#define CUT    5.0f
#define TR     16
#define WIN    11

typedef unsigned long long ull;

// scratch (no allocations allowed)
__device__ float  g_h[Natoms*Hdim];
__device__ __half g_hh[Natoms*Hdim];            // fp16 mirror of h
__device__ float  g_agg[Natoms*Hdim];
__device__ float  g_tmp[Natoms*Hdim];
__device__ float  g_G[NIs*NGRID*Hdim];          // gelu hidden of table MLP (all layers)
__device__ __half g_tab[NIs*NGRID*Hdim];        // fp16 filter tables (3 MB)
__device__ float  g_pool[Bmol*Hdim];
__device__ unsigned g_nbr[Natoms*Natoms];       // packed neighbor list
__device__ int      g_cnt[Natoms];

__device__ __forceinline__ float gelu_f(float x){
    return 0.5f*x*(1.0f+erff(x*0.70710678118654752f));
}
__device__ __forceinline__ void ffma2(ull& d, ull a, ull b){
    asm("fma.rn.f32x2 %0, %1, %2, %0;" : "+l"(d) : "l"(a), "l"(b));
}
__device__ __forceinline__ float2 unpk(ull v){
    float2 r; asm("mov.b64 {%0,%1}, %2;" : "=f"(r.x), "=f"(r.y) : "l"(v)); return r;
}

// ---------------------------------------------------------------- embedding
__global__ void k_embed(const int* __restrict__ z, const float* __restrict__ emb){
    int i=blockIdx.x, c=threadIdx.x;
    float v=emb[z[i]*Hdim+c];
    g_h[i*Hdim+c]=v;
    g_hh[i*Hdim+c]=__float2half(v);
}

// ------------------------------------------------ neighbor list (built once)
// packed: j(10) | r(11)<<10 | fq(11)<<21
__global__ void k_nbr(const float* __restrict__ pos){
    __shared__ int warp_cnt[8];
    int i=blockIdx.x, tid=threadIdx.x;
    float xi=pos[i*3+0], yi=pos[i*3+1], zi=pos[i*3+2];
    const float scale=(float)(NGRID-1)/CUT;
    int total=0;
    for(int base=0;base<Natoms;base+=256){
        int j=base+tid;
        float dx=pos[j*3+0]-xi;
        float dy=pos[j*3+1]-yi;
        float dz=pos[j*3+2]-zi;
        float d=sqrtf(dx*dx+dy*dy+dz*dz);
        bool keep=(j!=i)&&(d<CUT)&&(d>1e-6f);
        unsigned m=__ballot_sync(0xffffffffu,keep);
        if((tid&31)==0) warp_cnt[tid>>5]=__popc(m);
        __syncthreads();
        int off=total;
        int w=tid>>5;
        for(int ww=0;ww<w;ww++) off+=warp_cnt[ww];
        if(keep){
            int p=off+__popc(m&((1u<<(tid&31))-1u));
            float t=d*scale;
            int r=(int)t; if(r>NGRID-2)r=NGRID-2;
            float f=t-(float)r;
            int fq=(int)(f*2048.0f); if(fq>2047)fq=2047;
            g_nbr[i*Natoms+p]=(unsigned)j | ((unsigned)r<<10) | ((unsigned)fq<<21);
        }
        int bt=0;
        #pragma unroll
        for(int ww=0;ww<8;ww++) bt+=warp_cnt[ww];
        total+=bt;
        __syncthreads();
    }
    if(tid==0) g_cnt[i]=total;
}

// --------------------------------- table hidden: G = gelu(rbf @ fw1 + fb1)
// sparse gaussian window (11 wide); grid (NGRID/TR, NIs)
__global__ void k_hidden(const float* __restrict__ fw1all, const float* __restrict__ fb1all){
    __shared__ float rbf[TR][WIN+1];
    __shared__ int s_base;
    int layer=blockIdx.y;
    const float* fw1=fw1all+layer*NGs*Hdim;
    const float* fb1=fb1all+layer*Hdim;
    int r0=blockIdx.x*TR, c=threadIdx.x;
    const float dstep  = CUT/(float)(NGRID-1);
    const float cstep  = CUT/(float)(NGs-1);
    const float inv2w2 = 1.0f/(2.0f*0.05f*0.05f);

    if(c==0){
        float dmid=((float)r0+7.5f)*dstep;
        int b0=(int)(dmid/cstep+0.5f)-(WIN/2);
        s_base=b0;
    }
    __syncthreads();
    int base=s_base;
    for(int t=c;t<TR*WIN;t+=256){
        int row=t/WIN, g=t%WIN;
        int gi=base+g;
        float d=(float)(r0+row)*dstep;
        float u=d-(float)gi*cstep;
        float v=expf(-u*u*inv2w2);
        rbf[row][g]=(gi>=0 && gi<NGs)?v:0.0f;
    }
    __syncthreads();
    float acc[TR];
    float b1=fb1[c];
    #pragma unroll
    for(int t=0;t<TR;t++) acc[t]=b1;
    #pragma unroll
    for(int g=0;g<WIN;g++){
        int gi=base+g;
        gi=(gi<0)?0:((gi>NGs-1)?NGs-1:gi);
        float w=fw1[gi*Hdim+c];
        #pragma unroll
        for(int t=0;t<TR;t++) acc[t]=fmaf(rbf[t][g],w,acc[t]);
    }
    float* G=g_G+layer*NGRID*Hdim;
    #pragma unroll
    for(int t=0;t<TR;t++) G[(r0+t)*Hdim+c]=gelu_f(acc[t]);
}

// --------------------------- GEMM  C = act(A@W + b) [+Res], 64x64 tiles
// 256 threads, 4x4 micro-tile, k-pair-packed fma.rn.f32x2, conflict-free smem.
// LAYERED: blockIdx.z selects layer (A,W,bias,outputs offset).
template<bool GELU,bool RES,bool HALF_OUT,bool WRITEH,bool LAYERED,int MROWS>
__global__ void __launch_bounds__(256) k_gemm(const float* __restrict__ A,
                       const float* __restrict__ W,
                       const float* __restrict__ bias,
                       const float* __restrict__ Res,
                       float* __restrict__ Cf, __half* __restrict__ Ch){
    __shared__ ull As2[8][66];
    __shared__ ull Bs2[8][66];
    if(LAYERED){
        int L=blockIdx.z;
        A   += (size_t)L*MROWS*Hdim;
        W   += (size_t)L*Hdim*Hdim;
        bias+= (size_t)L*Hdim;
        if(HALF_OUT) Ch += (size_t)L*MROWS*Hdim;
        else         Cf += (size_t)L*MROWS*Hdim;
    }
    int m0=blockIdx.x*64, n0=blockIdx.y*64;
    int tid=threadIdx.x;
    int tm=tid>>4;          // 0..15 -> rows tm*4..tm*4+3
    int tn=tid&15;          // cols tn + v*16
    ull acc[4][4];
    #pragma unroll
    for(int u=0;u<4;u++)
        #pragma unroll
        for(int v=0;v<4;v++) acc[u][v]=0ull;

    // fill index precompute
    int ar=tid>>2, ak=(tid&3)<<2;            // A fill: row ar, k ak..ak+3
    int bkp=tid>>5, bn2=(tid&31)<<1;         // B fill: k-pair bkp, cols bn2,bn2+1

    for(int k0=0;k0<Hdim;k0+=16){
        float4 av=*reinterpret_cast<const float4*>(&A[(m0+ar)*Hdim+k0+ak]);
        {
            ull lo, hi;
            asm("mov.b64 %0, {%1,%2};":"=l"(lo):"f"(av.x),"f"(av.y));
            asm("mov.b64 %0, {%1,%2};":"=l"(hi):"f"(av.z),"f"(av.w));
            As2[(ak>>1)+0][ar]=lo;
            As2[(ak>>1)+1][ar]=hi;
        }
        {
            float2 w0=*reinterpret_cast<const float2*>(&W[(k0+2*bkp  )*Hdim+n0+bn2]);
            float2 w1=*reinterpret_cast<const float2*>(&W[(k0+2*bkp+1)*Hdim+n0+bn2]);
            ull p0,p1;
            asm("mov.b64 %0, {%1,%2};":"=l"(p0):"f"(w0.x),"f"(w1.x));
            asm("mov.b64 %0, {%1,%2};":"=l"(p1):"f"(w0.y),"f"(w1.y));
            Bs2[bkp][bn2+0]=p0;
            Bs2[bkp][bn2+1]=p1;
        }
        __syncthreads();
        #pragma unroll
        for(int kp=0;kp<8;kp++){
            ull a[4],b[4];
            #pragma unroll
            for(int u=0;u<4;u++) a[u]=As2[kp][tm*4+u];
            #pragma unroll
            for(int v=0;v<4;v++) b[v]=Bs2[kp][tn+v*16];
            #pragma unroll
            for(int u=0;u<4;u++)
                #pragma unroll
                for(int v=0;v<4;v++) ffma2(acc[u][v],a[u],b[v]);
        }
        __syncthreads();
    }
    #pragma unroll
    for(int u=0;u<4;u++){
        int row=m0+tm*4+u;
        #pragma unroll
        for(int v=0;v<4;v++){
            int col=n0+tn+v*16;
            float2 s=unpk(acc[u][v]);
            float x=s.x+s.y+bias[col];
            if(GELU) x=gelu_f(x);
            if(RES)  x+=Res[row*Hdim+col];
            if(HALF_OUT) Ch[row*Hdim+col]=__float2half(x);
            else         Cf[row*Hdim+col]=x;
            if(WRITEH)   g_hh[row*Hdim+col]=__float2half(x);
        }
    }
}

// ----------------------------------------- neighbor aggregation (fp16 lerp)
__global__ void __launch_bounds__(128) k_agg(const __half2* __restrict__ tab){
    __shared__ unsigned lst[Natoms];
    int i=blockIdx.x, tid=threadIdx.x;
    int total=g_cnt[i];
    for(int t=tid;t<total;t+=128) lst[t]=g_nbr[i*Natoms+t];
    __syncthreads();
    const __half2* __restrict__ hh =reinterpret_cast<const __half2*>(g_hh);
    int c=tid;                 // half2 channel index 0..127
    float ax=0.f, ay=0.f;
    #pragma unroll 8
    for(int n=0;n<total;n++){
        unsigned p=lst[n];
        int j=p&1023;
        int r=(p>>10)&2047;
        float f=(float)(p>>21)*(1.0f/2048.0f);
        __half2 w0=__ldg(&tab[r*128+c]);
        __half2 w1=__ldg(&tab[(r+1)*128+c]);
        __half2 hv=__ldg(&hh[j*128+c]);
        float2 a0=__half22float2(w0);
        float2 a1=__half22float2(w1);
        float2 hf=__half22float2(hv);
        float wx=fmaf(f,a1.x-a0.x,a0.x);
        float wy=fmaf(f,a1.y-a0.y,a0.y);
        ax=fmaf(wx,hf.x,ax);
        ay=fmaf(wy,hf.y,ay);
    }
    g_agg[i*Hdim+2*c+0]=ax;
    g_agg[i*Hdim+2*c+1]=ay;
}

// ---------------------------------------------------------------- pooling
__global__ void k_pool(const int* __restrict__ batch){
    int b=blockIdx.x, c=threadIdx.x;
    float s=0.f;
    #pragma unroll 8
    for(int i=0;i<Natoms;i++){
        s += (batch[i]==b) ? g_h[i*Hdim+c] : 0.f;
    }
    g_pool[b*Hdim+c]=s;
}

// ------------------------------------------------- projection head + layernorm
__global__ void k_head(const float* __restrict__ pw1,const float* __restrict__ pb1,
                       const float* __restrict__ pw2,const float* __restrict__ pb2,
                       const float* __restrict__ lng,const float* __restrict__ lnb,
                       float* __restrict__ out){
    __shared__ float pv[Hdim];
    __shared__ float tv[Hdim];
    __shared__ float xv[Ldim];
    __shared__ float red[8];
    __shared__ float s_mu, s_inv;
    int b=blockIdx.x, tid=threadIdx.x;
    pv[tid]=g_pool[b*Hdim+tid];
    __syncthreads();
    float a=pb1[tid];
    for(int k=0;k<Hdim;k++) a=fmaf(pv[k],pw1[k*Hdim+tid],a);
    tv[tid]=gelu_f(a);
    __syncthreads();
    for(int o=tid;o<Ldim;o+=256){
        float x=pb2[o];
        for(int k=0;k<Hdim;k++) x=fmaf(tv[k],pw2[k*Ldim+o],x);
        xv[o]=x;
    }
    __syncthreads();
    float s=xv[tid]+xv[tid+256];
    for(int d=16;d>0;d>>=1) s+=__shfl_down_sync(0xffffffffu,s,d);
    if((tid&31)==0) red[tid>>5]=s;
    __syncthreads();
    if(tid==0){
        float t=0.f; for(int w=0;w<8;w++) t+=red[w];
        s_mu=t/(float)Ldim;
    }
    __syncthreads();
    float mu=s_mu;
    float d0=xv[tid]-mu, d1=xv[tid+256]-mu;
    float s2=d0*d0+d1*d1;
    for(int d=16;d>0;d>>=1) s2+=__shfl_down_sync(0xffffffffu,s2,d);
    if((tid&31)==0) red[tid>>5]=s2;
    __syncthreads();
    if(tid==0){
        float t=0.f; for(int w=0;w<8;w++) t+=red[w];
        s_inv=1.0f/sqrtf(t/(float)Ldim + 1e-5f);
    }
    __syncthreads();
    float inv=s_inv;
    out[b*Ldim+tid]     =(xv[tid]-mu)*inv*lng[tid]+lnb[tid];
    out[b*Ldim+tid+256] =(xv[tid+256]-mu)*inv*lng[tid+256]+lnb[tid+256];
}

// ------------------------------------------------------------------ launcher
extern "C" void kernel_launch(void* const* d_in, const int* in_sizes, int n_in,
                              void* d_out, int out_size){
    const int*   z    =(const int*)  d_in[0];
    const float* pos  =(const float*)d_in[1];
    const int*   batch=(const int*)  d_in[2];
    const float* emb  =(const float*)d_in[3];
    const float* fw1  =(const float*)d_in[4];
    const float* fb1  =(const float*)d_in[5];
    const float* fw2  =(const float*)d_in[6];
    const float* fb2  =(const float*)d_in[7];
    const float* aw1  =(const float*)d_in[8];
    const float* ab1  =(const float*)d_in[9];
    const float* aw2  =(const float*)d_in[10];
    const float* ab2  =(const float*)d_in[11];
    const float* pw1  =(const float*)d_in[12];
    const float* pb1  =(const float*)d_in[13];
    const float* pw2  =(const float*)d_in[14];
    const float* pb2  =(const float*)d_in[15];
    const float* lng  =(const float*)d_in[16];
    const float* lnb  =(const float*)d_in[17];
    float* out=(float*)d_out;

    float *pagg,*ptmp,*ph,*pG;
    __half *ptab;
    cudaGetSymbolAddress((void**)&pagg,g_agg);
    cudaGetSymbolAddress((void**)&ptmp,g_tmp);
    cudaGetSymbolAddress((void**)&ph,  g_h);
    cudaGetSymbolAddress((void**)&pG,  g_G);
    cudaGetSymbolAddress((void**)&ptab,g_tab);

    k_embed<<<Natoms,Hdim>>>(z,emb);
    k_nbr<<<Natoms,256>>>(pos);
    // build all 3 layers' filter tables upfront
    k_hidden<<<dim3(NGRID/TR,NIs),Hdim>>>(fw1,fb1);
    k_gemm<false,false,true ,false,true ,NGRID><<<dim3(NGRID/64,Hdim/64,NIs),256>>>(pG, fw2, fb2, nullptr, nullptr, ptab);
    for(int l=0;l<NIs;l++){
        k_agg<<<Natoms,128>>>(reinterpret_cast<const __half2*>(ptab)+(size_t)l*NGRID*Hdim/2);
        k_gemm<true ,false,false,false,false,Natoms><<<dim3(Natoms/64,Hdim/64),256>>>(pagg, aw1+l*Hdim*Hdim, ab1+l*Hdim, nullptr, ptmp, nullptr);
        k_gemm<false,true ,false,true ,false,Natoms><<<dim3(Natoms/64,Hdim/64),256>>>(ptmp, aw2+l*Hdim*Hdim, ab2+l*Hdim, ph, ph, nullptr);
    }
    k_pool<<<Bmol,Hdim>>>(batch);
    k_head<<<Bmol,Hdim>>>(pw1,pb1,pw2,pb2,lng,lnb,out);
}